// round 5
// baseline (speedup 1.0000x reference)
#include <cuda_runtime.h>
#include <cstdint>

#define Nn 50000
#define Ee 800000
#define FIN 256
#define F1 32
#define H1 8
#define NHID 256
#define NC 47

// ---------------- scratch (device globals: allocation-free) ----------------
__device__ int   g_rowptr[Nn + 1];
__device__ int   g_cursor[Nn];
__device__ int   g_csr_dst[Ee];
__device__ int   g_bsums[64];
__device__ float g_h1[Nn * F1];          // 6.4 MB  (L2 resident)
__device__ float g_el1[Nn * H1];
__device__ float g_er1[Nn * H1];
__device__ float g_r1[Nn * NHID];        // 51.2 MB
__device__ float g_h2[Nn * NC];          // 9.4 MB  (L2 resident)
__device__ float g_el2[Nn];
__device__ float g_er2[Nn];
__device__ float g_B1ext[FIN * 48];      // [W1 | W1@Wl1 | W1@Wr1]
__device__ float g_B2ext[FIN * 49];      // [W2 | W2@Wl2 | W2@Wr2]

// ---------------- tf32 mma helpers ----------------
__device__ __forceinline__ uint32_t f2tf32(float f) {
    uint32_t r;
    asm("cvt.rna.tf32.f32 %0, %1;" : "=r"(r) : "f"(f));
    return r;
}

__device__ __forceinline__ void mma_tf32(float* d,
    uint32_t a0, uint32_t a1, uint32_t a2, uint32_t a3,
    uint32_t b0, uint32_t b1) {
    asm volatile(
        "mma.sync.aligned.m16n8k8.row.col.f32.tf32.tf32.f32 "
        "{%0,%1,%2,%3},{%4,%5,%6,%7},{%8,%9},{%0,%1,%2,%3};\n"
        : "+f"(d[0]), "+f"(d[1]), "+f"(d[2]), "+f"(d[3])
        : "r"(a0), "r"(a1), "r"(a2), "r"(a3), "r"(b0), "r"(b1));
}

// ---------------- prep: extended B matrices ----------------
__global__ void k_prep1(const float* __restrict__ W1, const float* __restrict__ Wl1,
                        const float* __restrict__ Wr1) {
    __shared__ float swl[F1 * H1], swr[F1 * H1];
    int k = threadIdx.x;              // 0..255
    swl[k] = Wl1[k];
    swr[k] = Wr1[k];
    __syncthreads();
    float row[F1];
    #pragma unroll
    for (int j = 0; j < F1; j++) row[j] = W1[k * F1 + j];
    #pragma unroll
    for (int j = 0; j < F1; j++) g_B1ext[k * 48 + j] = row[j];
    #pragma unroll
    for (int h = 0; h < H1; h++) {
        float sl = 0.f, sr = 0.f;
        #pragma unroll
        for (int j = 0; j < F1; j++) {
            sl = fmaf(row[j], swl[j * H1 + h], sl);
            sr = fmaf(row[j], swr[j * H1 + h], sr);
        }
        g_B1ext[k * 48 + 32 + h] = sl;
        g_B1ext[k * 48 + 40 + h] = sr;
    }
}

__global__ void k_prep2(const float* __restrict__ W2, const float* __restrict__ Wl2,
                        const float* __restrict__ Wr2) {
    __shared__ float swl[NC], swr[NC];
    int k = threadIdx.x;              // 0..255
    if (k < NC) { swl[k] = Wl2[k]; swr[k] = Wr2[k]; }
    __syncthreads();
    float row[NC];
    #pragma unroll
    for (int j = 0; j < NC; j++) row[j] = W2[k * NC + j];
    #pragma unroll
    for (int j = 0; j < NC; j++) g_B2ext[k * 49 + j] = row[j];
    float sl = 0.f, sr = 0.f;
    #pragma unroll
    for (int j = 0; j < NC; j++) {
        sl = fmaf(row[j], swl[j], sl);
        sr = fmaf(row[j], swr[j], sr);
    }
    g_B2ext[k * 49 + 47] = sl;
    g_B2ext[k * 49 + 48] = sr;
}

// ---------------- CSR build ----------------
__global__ void k_zero_counts() {
    int i = blockIdx.x * blockDim.x + threadIdx.x;
    if (i < Nn + 1) g_rowptr[i] = 0;
}

__global__ void k_count(const int* __restrict__ src) {
    int e = blockIdx.x * blockDim.x + threadIdx.x;
    if (e < Ee) atomicAdd(&g_rowptr[src[e]], 1);
}

__global__ void k_scan_blocks(int n) {
    __shared__ int wsum[32];
    int tid = threadIdx.x;
    int gid = blockIdx.x * 1024 + tid;
    int v = (gid < n) ? g_rowptr[gid] : 0;
    int lane = tid & 31, wid = tid >> 5;
    int x = v;
    #pragma unroll
    for (int d = 1; d < 32; d <<= 1) {
        int t = __shfl_up_sync(0xffffffffu, x, d);
        if (lane >= d) x += t;
    }
    if (lane == 31) wsum[wid] = x;
    __syncthreads();
    if (wid == 0) {
        int w = wsum[lane];
        #pragma unroll
        for (int d = 1; d < 32; d <<= 1) {
            int t = __shfl_up_sync(0xffffffffu, w, d);
            if (lane >= d) w += t;
        }
        wsum[lane] = w;
    }
    __syncthreads();
    int incl = x + (wid > 0 ? wsum[wid - 1] : 0);
    if (gid < n) g_rowptr[gid] = incl - v;   // exclusive
    if (tid == 1023) g_bsums[blockIdx.x] = incl;
}

__global__ void k_finalize_scan(int n) {
    __shared__ int soff;
    int tid = threadIdx.x;
    if (tid < 32) {
        int v1 = (tid      < (int)blockIdx.x) ? g_bsums[tid]      : 0;
        int v2 = (tid + 32 < (int)blockIdx.x) ? g_bsums[tid + 32] : 0;
        int s = v1 + v2;
        #pragma unroll
        for (int d = 16; d > 0; d >>= 1) s += __shfl_xor_sync(0xffffffffu, s, d);
        if (tid == 0) soff = s;
    }
    __syncthreads();
    int gid = blockIdx.x * 1024 + tid;
    if (gid < n) {
        int v = g_rowptr[gid] + soff;
        g_rowptr[gid] = v;
        if (gid < Nn) g_cursor[gid] = v;
    }
}

__global__ void k_scatter(const int* __restrict__ src, const int* __restrict__ dst) {
    int e = blockIdx.x * blockDim.x + threadIdx.x;
    if (e < Ee) {
        int s = src[e];
        int pos = atomicAdd(&g_cursor[s], 1);
        g_csr_dst[pos] = dst[e];
    }
}

// ---------------- GEMM1 (tf32 mma, fused h1/el1/er1) ----------------
// N=48: nt 0..3 -> h1, nt 4 -> el1, nt 5 -> er1. Software-pipelined A loads.
// stride S1 = 50 (S ≡ 2 mod 8 keeps permuted B reads bank-bijective).
#define S1 50
__global__ void __launch_bounds__(256) k_gemm1(const float* __restrict__ x) {
    extern __shared__ uint32_t sm1[];
    uint32_t* sB = sm1;                      // [256][S1]
    int tx = threadIdx.x, lane = tx & 31, w = tx >> 5;
    for (int i = tx; i < FIN * 48; i += 256) {
        int k = i / 48, n = i - k * 48;
        sB[k * S1 + n] = f2tf32(g_B1ext[i]);
    }
    __syncthreads();

    int g = lane >> 2, c = lane & 3;
    int row0 = blockIdx.x * 128 + w * 16 + g;
    int row1 = row0 + 8;
    bool v0 = row0 < Nn, v1 = row1 < Nn;
    const float4* A0 = (const float4*)(x + (size_t)row0 * FIN);
    const float4* A1 = (const float4*)(x + (size_t)row1 * FIN);
    const float4 z4 = make_float4(0.f, 0.f, 0.f, 0.f);

    float acc[6][4];
    #pragma unroll
    for (int nt = 0; nt < 6; nt++)
        #pragma unroll
        for (int j = 0; j < 4; j++) acc[nt][j] = 0.f;

    float4 cur0 = v0 ? A0[c] : z4;
    float4 cur1 = v1 ? A1[c] : z4;
    #pragma unroll 4
    for (int wnd = 0; wnd < 16; wnd++) {
        float4 nxt0 = (v0 && wnd < 15) ? A0[(wnd + 1) * 4 + c] : z4;
        float4 nxt1 = (v1 && wnd < 15) ? A1[(wnd + 1) * 4 + c] : z4;
        uint32_t a00 = f2tf32(cur0.x), a01 = f2tf32(cur0.y), a02 = f2tf32(cur0.z), a03 = f2tf32(cur0.w);
        uint32_t a10 = f2tf32(cur1.x), a11 = f2tf32(cur1.y), a12 = f2tf32(cur1.z), a13 = f2tf32(cur1.w);
        const uint32_t* bA = sB + (wnd * 16 + 4 * c) * S1;
        #pragma unroll
        for (int nt = 0; nt < 6; nt++) {
            mma_tf32(acc[nt], a00, a10, a01, a11, bA[nt * 8 + g], bA[S1 + nt * 8 + g]);
        }
        #pragma unroll
        for (int nt = 0; nt < 6; nt++) {
            mma_tf32(acc[nt], a02, a12, a03, a13, bA[2 * S1 + nt * 8 + g], bA[3 * S1 + nt * 8 + g]);
        }
        cur0 = nxt0; cur1 = nxt1;
    }
    #pragma unroll
    for (int nt = 0; nt < 4; nt++) {
        int col = nt * 8 + c * 2;
        if (v0) *(float2*)&g_h1[row0 * F1 + col] = make_float2(acc[nt][0], acc[nt][1]);
        if (v1) *(float2*)&g_h1[row1 * F1 + col] = make_float2(acc[nt][2], acc[nt][3]);
    }
    // nt=4 -> el1 heads 2c,2c+1 ; nt=5 -> er1
    if (v0) *(float2*)&g_el1[row0 * H1 + 2 * c] = make_float2(acc[4][0], acc[4][1]);
    if (v1) *(float2*)&g_el1[row1 * H1 + 2 * c] = make_float2(acc[4][2], acc[4][3]);
    if (v0) *(float2*)&g_er1[row0 * H1 + 2 * c] = make_float2(acc[5][0], acc[5][1]);
    if (v1) *(float2*)&g_er1[row1 * H1 + 2 * c] = make_float2(acc[5][2], acc[5][3]);
}

// ---------------- GEMM2 (tf32 mma, fused h2/el2/er2) ----------------
// N=56 (7 n-tiles); cols 0..46 -> h2, 47 -> el2, 48 -> er2, 49..55 pad.
#define S2 58
__global__ void __launch_bounds__(256) k_gemm2() {
    extern __shared__ uint32_t sm2[];
    uint32_t* sB = sm2;                      // [256][S2]
    int tx = threadIdx.x, lane = tx & 31, w = tx >> 5;
    for (int k = 0; k < FIN; k += 4) {       // zero pad cols 49..55
        int kk = k + (tx >> 6);
        int n = 49 + (tx & 63);
        if (n < S2) sB[kk * S2 + n] = 0u;
    }
    for (int i = tx; i < FIN * 49; i += 256) {
        int k = i / 49, n = i - k * 49;
        sB[k * S2 + n] = f2tf32(g_B2ext[i]);
    }
    __syncthreads();

    int g = lane >> 2, c = lane & 3;
    int row0 = blockIdx.x * 128 + w * 16 + g;
    int row1 = row0 + 8;
    bool v0 = row0 < Nn, v1 = row1 < Nn;
    const float4* A0 = (const float4*)(g_r1 + (size_t)row0 * FIN);
    const float4* A1 = (const float4*)(g_r1 + (size_t)row1 * FIN);
    const float4 z4 = make_float4(0.f, 0.f, 0.f, 0.f);

    float acc[7][4];
    #pragma unroll
    for (int nt = 0; nt < 7; nt++)
        #pragma unroll
        for (int j = 0; j < 4; j++) acc[nt][j] = 0.f;

    float4 cur0 = v0 ? A0[c] : z4;
    float4 cur1 = v1 ? A1[c] : z4;
    #pragma unroll 2
    for (int wnd = 0; wnd < 16; wnd++) {
        float4 nxt0 = (v0 && wnd < 15) ? A0[(wnd + 1) * 4 + c] : z4;
        float4 nxt1 = (v1 && wnd < 15) ? A1[(wnd + 1) * 4 + c] : z4;
        uint32_t a00 = f2tf32(cur0.x), a01 = f2tf32(cur0.y), a02 = f2tf32(cur0.z), a03 = f2tf32(cur0.w);
        uint32_t a10 = f2tf32(cur1.x), a11 = f2tf32(cur1.y), a12 = f2tf32(cur1.z), a13 = f2tf32(cur1.w);
        const uint32_t* bA = sB + (wnd * 16 + 4 * c) * S2;
        #pragma unroll
        for (int nt = 0; nt < 7; nt++) {
            mma_tf32(acc[nt], a00, a10, a01, a11, bA[nt * 8 + g], bA[S2 + nt * 8 + g]);
        }
        #pragma unroll
        for (int nt = 0; nt < 7; nt++) {
            mma_tf32(acc[nt], a02, a12, a03, a13, bA[2 * S2 + nt * 8 + g], bA[3 * S2 + nt * 8 + g]);
        }
        cur0 = nxt0; cur1 = nxt1;
    }
    #pragma unroll
    for (int nt = 0; nt < 7; nt++) {
        int col = nt * 8 + c * 2;
        if (col + 1 < NC) {                          // plain h2 pair
            if (v0) { g_h2[(size_t)row0 * NC + col] = acc[nt][0]; g_h2[(size_t)row0 * NC + col + 1] = acc[nt][1]; }
            if (v1) { g_h2[(size_t)row1 * NC + col] = acc[nt][2]; g_h2[(size_t)row1 * NC + col + 1] = acc[nt][3]; }
        } else if (col == 46) {                      // h2[46] + el2
            if (v0) { g_h2[(size_t)row0 * NC + 46] = acc[nt][0]; g_el2[row0] = acc[nt][1]; }
            if (v1) { g_h2[(size_t)row1 * NC + 46] = acc[nt][2]; g_el2[row1] = acc[nt][3]; }
        } else if (col == 48) {                      // er2
            if (v0) g_er2[row0] = acc[nt][0];
            if (v1) g_er2[row1] = acc[nt][2];
        }
    }
}

// ---------------- layer-1 aggregation + bias + ELU -> r1 ----------------
__global__ void k_agg1(const float* __restrict__ b1) {
    __shared__ float ws[8][32 * 8];    // [warp][edge][head] weights
    int wid = threadIdx.x >> 5, lane = threadIdx.x & 31;
    int i = blockIdx.x * 8 + wid;

    float el_own = (lane < H1) ? g_el1[i * H1 + lane] : 0.f;
    float elh[H1];
    #pragma unroll
    for (int h = 0; h < H1; h++) elh[h] = __shfl_sync(0xffffffffu, el_own, h);

    float acc[H1], denp[H1];
    #pragma unroll
    for (int h = 0; h < H1; h++) { acc[h] = 0.f; denp[h] = 0.f; }

    int beg = g_rowptr[i], end = g_rowptr[i + 1];
    for (int base = beg; base < end; base += 32) {
        int nb = min(32, end - base);
        int dstl = (lane < nb) ? g_csr_dst[base + lane] : 0;
        float w_own[H1];
        if (lane < nb) {
            const float4* er4 = (const float4*)(g_er1 + (size_t)dstl * H1);
            float4 ea = er4[0], eb = er4[1];
            float er_[H1] = {ea.x, ea.y, ea.z, ea.w, eb.x, eb.y, eb.z, eb.w};
            #pragma unroll
            for (int h = 0; h < H1; h++) {
                float a = elh[h] + er_[h];
                float lr = a > 0.f ? a : 0.2f * a;
                float wv = __expf(lr);
                w_own[h] = wv;
                denp[h] += wv;
            }
        } else {
            #pragma unroll
            for (int h = 0; h < H1; h++) w_own[h] = 0.f;
        }
        float4* wrow = (float4*)&ws[wid][lane * 8];
        wrow[0] = make_float4(w_own[0], w_own[1], w_own[2], w_own[3]);
        wrow[1] = make_float4(w_own[4], w_own[5], w_own[6], w_own[7]);
        __syncwarp();
        for (int j = 0; j < nb; j++) {
            int dst = __shfl_sync(0xffffffffu, dstl, j);
            float hv = g_h1[dst * F1 + lane];
            const float4* wj = (const float4*)&ws[wid][j * 8];
            float4 wa = wj[0], wb = wj[1];
            acc[0] = fmaf(wa.x, hv, acc[0]);
            acc[1] = fmaf(wa.y, hv, acc[1]);
            acc[2] = fmaf(wa.z, hv, acc[2]);
            acc[3] = fmaf(wa.w, hv, acc[3]);
            acc[4] = fmaf(wb.x, hv, acc[4]);
            acc[5] = fmaf(wb.y, hv, acc[5]);
            acc[6] = fmaf(wb.z, hv, acc[6]);
            acc[7] = fmaf(wb.w, hv, acc[7]);
        }
        __syncwarp();
    }
    float bb = b1[lane];
    #pragma unroll
    for (int h = 0; h < H1; h++) {
        float t = denp[h];
        #pragma unroll
        for (int d = 16; d > 0; d >>= 1) t += __shfl_xor_sync(0xffffffffu, t, d);
        float o = acc[h] / fmaxf(t, 1e-12f) + bb;
        float e = o > 0.f ? o : (__expf(o) - 1.f);   // ELU
        g_r1[(size_t)i * NHID + h * F1 + lane] = e;
    }
}

// ---------------- layer-2 aggregation + bias + log_softmax -> out ----------------
__global__ void k_agg2(const float* __restrict__ b2, float* __restrict__ out) {
    int wid = threadIdx.x >> 5, lane = threadIdx.x & 31;
    int i = blockIdx.x * 8 + wid;
    float el = g_el2[i];
    float acc0 = 0.f, acc1 = 0.f, denp = 0.f;
    int beg = g_rowptr[i], end = g_rowptr[i + 1];
    for (int base = beg; base < end; base += 32) {
        int nb = min(32, end - base);
        int dstl = (lane < nb) ? g_csr_dst[base + lane] : 0;
        float wl_ = 0.f;
        if (lane < nb) {
            float a = el + g_er2[dstl];
            float lr = a > 0.f ? a : 0.2f * a;
            wl_ = __expf(lr);
            denp += wl_;
        }
        for (int j = 0; j < nb; j++) {
            int dst = __shfl_sync(0xffffffffu, dstl, j);
            float w = __shfl_sync(0xffffffffu, wl_, j);
            acc0 = fmaf(w, g_h2[(size_t)dst * NC + lane], acc0);
            if (lane < NC - 32)
                acc1 = fmaf(w, g_h2[(size_t)dst * NC + 32 + lane], acc1);
        }
    }
    float den = denp;
    #pragma unroll
    for (int d = 16; d > 0; d >>= 1) den += __shfl_xor_sync(0xffffffffu, den, d);
    den = fmaxf(den, 1e-12f);
    float v0 = acc0 / den + b2[lane];
    float v1 = (lane < NC - 32) ? (acc1 / den + b2[32 + lane]) : -3.0e38f;
    float m = fmaxf(v0, v1);
    #pragma unroll
    for (int d = 16; d > 0; d >>= 1) m = fmaxf(m, __shfl_xor_sync(0xffffffffu, m, d));
    float s = __expf(v0 - m) + ((lane < NC - 32) ? __expf(v1 - m) : 0.f);
    #pragma unroll
    for (int d = 16; d > 0; d >>= 1) s += __shfl_xor_sync(0xffffffffu, s, d);
    float ls = logf(s);
    out[(size_t)i * NC + lane] = v0 - m - ls;
    if (lane < NC - 32) out[(size_t)i * NC + 32 + lane] = v1 - m - ls;
}

// ---------------- launch ----------------
extern "C" void kernel_launch(void* const* d_in, const int* in_sizes, int n_in,
                              void* d_out, int out_size) {
    const float* x    = (const float*)d_in[0];
    const int*   esrc = (const int*)  d_in[1];
    const int*   edst = (const int*)  d_in[2];
    const float* W1   = (const float*)d_in[3];
    const float* Wl1  = (const float*)d_in[4];
    const float* Wr1  = (const float*)d_in[5];
    const float* b1   = (const float*)d_in[6];
    const float* W2   = (const float*)d_in[7];
    const float* Wl2  = (const float*)d_in[8];
    const float* Wr2  = (const float*)d_in[9];
    const float* b2   = (const float*)d_in[10];
    float* out = (float*)d_out;

    const int smem1 = FIN * S1 * 4;   // 50 KB
    const int smem2 = FIN * S2 * 4;   // 58 KB
    cudaFuncSetAttribute(k_gemm1, cudaFuncAttributeMaxDynamicSharedMemorySize, smem1);
    cudaFuncSetAttribute(k_gemm2, cudaFuncAttributeMaxDynamicSharedMemorySize, smem2);

    int n_scan = Nn + 1;
    int nb = (n_scan + 1023) / 1024;           // 49

    // order chosen so launch #4 (the profiled slot) = k_gemm1
    k_prep1<<<1, 256>>>(W1, Wl1, Wr1);
    k_zero_counts<<<(Nn + 1 + 255) / 256, 256>>>();
    k_count<<<Ee / 256, 256>>>(esrc);
    k_gemm1<<<(Nn + 127) / 128, 256, smem1>>>(x);   // #4 <- profiled
    k_scan_blocks<<<nb, 1024>>>(n_scan);
    k_finalize_scan<<<nb, 1024>>>(n_scan);
    k_scatter<<<Ee / 256, 256>>>(esrc, edst);
    k_agg1<<<Nn / 8, 256>>>(b1);

    k_prep2<<<1, 256>>>(W2, Wl2, Wr2);
    k_gemm2<<<(Nn + 127) / 128, 256, smem2>>>();
    k_agg2<<<Nn / 8, 256>>>(b2, out);
}

// round 6
// speedup vs baseline: 1.0226x; 1.0226x over previous
#include <cuda_runtime.h>
#include <cstdint>

#define Nn 50000
#define Ee 800000
#define FIN 256
#define F1 32
#define H1 8
#define NHID 256
#define NC 47

// ---------------- scratch (device globals: allocation-free) ----------------
__device__ int   g_rowptr[Nn + 1];
__device__ int   g_cursor[Nn];
__device__ int   g_csr_dst[Ee];
__device__ int   g_bsums[64];
__device__ float g_h1[Nn * F1];          // 6.4 MB  (L2 resident)
__device__ float g_el1[Nn * H1];
__device__ float g_er1[Nn * H1];
__device__ float g_r1[Nn * NHID];        // 51.2 MB
__device__ float g_h2p[Nn * 48];         // padded h2 (48 cols), 9.6 MB
__device__ float g_el2[Nn];
__device__ float g_er2[Nn];
__device__ float g_B1ext[FIN * 48];      // [W1 | W1@Wl1 | W1@Wr1]
__device__ float g_B2ext[FIN * 50];      // [W2 | 0pad | W2@Wl2 | W2@Wr2]

// ---------------- tf32 mma helpers ----------------
__device__ __forceinline__ uint32_t f2tf32(float f) {
    uint32_t r;
    asm("cvt.rna.tf32.f32 %0, %1;" : "=r"(r) : "f"(f));
    return r;
}

__device__ __forceinline__ void mma_tf32(float* d,
    uint32_t a0, uint32_t a1, uint32_t a2, uint32_t a3,
    uint32_t b0, uint32_t b1) {
    asm volatile(
        "mma.sync.aligned.m16n8k8.row.col.f32.tf32.tf32.f32 "
        "{%0,%1,%2,%3},{%4,%5,%6,%7},{%8,%9},{%0,%1,%2,%3};\n"
        : "+f"(d[0]), "+f"(d[1]), "+f"(d[2]), "+f"(d[3])
        : "r"(a0), "r"(a1), "r"(a2), "r"(a3), "r"(b0), "r"(b1));
}

// ---------------- prep: extended B matrices ----------------
__global__ void k_prep1(const float* __restrict__ W1, const float* __restrict__ Wl1,
                        const float* __restrict__ Wr1) {
    __shared__ float swl[F1 * H1], swr[F1 * H1];
    int k = threadIdx.x;              // 0..255
    swl[k] = Wl1[k];
    swr[k] = Wr1[k];
    __syncthreads();
    float row[F1];
    #pragma unroll
    for (int j = 0; j < F1; j++) row[j] = W1[k * F1 + j];
    #pragma unroll
    for (int j = 0; j < F1; j++) g_B1ext[k * 48 + j] = row[j];
    #pragma unroll
    for (int h = 0; h < H1; h++) {
        float sl = 0.f, sr = 0.f;
        #pragma unroll
        for (int j = 0; j < F1; j++) {
            sl = fmaf(row[j], swl[j * H1 + h], sl);
            sr = fmaf(row[j], swr[j * H1 + h], sr);
        }
        g_B1ext[k * 48 + 32 + h] = sl;
        g_B1ext[k * 48 + 40 + h] = sr;
    }
}

__global__ void k_prep2(const float* __restrict__ W2, const float* __restrict__ Wl2,
                        const float* __restrict__ Wr2) {
    __shared__ float swl[NC], swr[NC];
    int k = threadIdx.x;              // 0..255
    if (k < NC) { swl[k] = Wl2[k]; swr[k] = Wr2[k]; }
    __syncthreads();
    float row[NC];
    #pragma unroll
    for (int j = 0; j < NC; j++) row[j] = W2[k * NC + j];
    #pragma unroll
    for (int j = 0; j < NC; j++) g_B2ext[k * 50 + j] = row[j];
    g_B2ext[k * 50 + 47] = 0.f;
    float sl = 0.f, sr = 0.f;
    #pragma unroll
    for (int j = 0; j < NC; j++) {
        sl = fmaf(row[j], swl[j], sl);
        sr = fmaf(row[j], swr[j], sr);
    }
    g_B2ext[k * 50 + 48] = sl;
    g_B2ext[k * 50 + 49] = sr;
}

// ---------------- CSR build ----------------
__global__ void k_zero_counts() {
    int i = blockIdx.x * blockDim.x + threadIdx.x;
    if (i < Nn + 1) g_rowptr[i] = 0;
}

__global__ void k_count(const int* __restrict__ src) {
    int e = blockIdx.x * blockDim.x + threadIdx.x;
    if (e < Ee) atomicAdd(&g_rowptr[src[e]], 1);
}

__global__ void k_scan_blocks(int n) {
    __shared__ int wsum[32];
    int tid = threadIdx.x;
    int gid = blockIdx.x * 1024 + tid;
    int v = (gid < n) ? g_rowptr[gid] : 0;
    int lane = tid & 31, wid = tid >> 5;
    int x = v;
    #pragma unroll
    for (int d = 1; d < 32; d <<= 1) {
        int t = __shfl_up_sync(0xffffffffu, x, d);
        if (lane >= d) x += t;
    }
    if (lane == 31) wsum[wid] = x;
    __syncthreads();
    if (wid == 0) {
        int w = wsum[lane];
        #pragma unroll
        for (int d = 1; d < 32; d <<= 1) {
            int t = __shfl_up_sync(0xffffffffu, w, d);
            if (lane >= d) w += t;
        }
        wsum[lane] = w;
    }
    __syncthreads();
    int incl = x + (wid > 0 ? wsum[wid - 1] : 0);
    if (gid < n) g_rowptr[gid] = incl - v;   // exclusive
    if (tid == 1023) g_bsums[blockIdx.x] = incl;
}

__global__ void k_finalize_scan(int n) {
    __shared__ int soff;
    int tid = threadIdx.x;
    if (tid < 32) {
        int v1 = (tid      < (int)blockIdx.x) ? g_bsums[tid]      : 0;
        int v2 = (tid + 32 < (int)blockIdx.x) ? g_bsums[tid + 32] : 0;
        int s = v1 + v2;
        #pragma unroll
        for (int d = 16; d > 0; d >>= 1) s += __shfl_xor_sync(0xffffffffu, s, d);
        if (tid == 0) soff = s;
    }
    __syncthreads();
    int gid = blockIdx.x * 1024 + tid;
    if (gid < n) {
        int v = g_rowptr[gid] + soff;
        g_rowptr[gid] = v;
        if (gid < Nn) g_cursor[gid] = v;
    }
}

__global__ void k_scatter(const int* __restrict__ src, const int* __restrict__ dst) {
    int e = blockIdx.x * blockDim.x + threadIdx.x;
    if (e < Ee) {
        int s = src[e];
        int pos = atomicAdd(&g_cursor[s], 1);
        g_csr_dst[pos] = dst[e];
    }
}

// ---------------- GEMM1 (tf32 mma, fused h1/el1/er1, 4-window chunk prefetch) ----------------
#define S1 50
__global__ void __launch_bounds__(256) k_gemm1(const float* __restrict__ x) {
    extern __shared__ uint32_t sm1[];
    uint32_t* sB = sm1;                      // [256][S1]
    int tx = threadIdx.x, lane = tx & 31, w = tx >> 5;
    for (int i = tx; i < FIN * 48; i += 256) {
        int k = i / 48, n = i - k * 48;
        sB[k * S1 + n] = f2tf32(g_B1ext[i]);
    }
    __syncthreads();

    int g = lane >> 2, c = lane & 3;
    int row0 = blockIdx.x * 128 + w * 16 + g;
    int row1 = row0 + 8;
    bool v0 = row0 < Nn, v1 = row1 < Nn;
    const float4* A0 = (const float4*)(x + (size_t)row0 * FIN);
    const float4* A1 = (const float4*)(x + (size_t)row1 * FIN);
    const float4 z4 = make_float4(0.f, 0.f, 0.f, 0.f);

    float acc[6][4];
    #pragma unroll
    for (int nt = 0; nt < 6; nt++)
        #pragma unroll
        for (int j = 0; j < 4; j++) acc[nt][j] = 0.f;

    float4 b0[4], b1[4];
    #pragma unroll
    for (int t = 0; t < 4; t++) {
        b0[t] = v0 ? A0[t * 4 + c] : z4;
        b1[t] = v1 ? A1[t * 4 + c] : z4;
    }
    #pragma unroll
    for (int ch = 0; ch < 4; ch++) {
        float4 n0[4], n1[4];
        #pragma unroll
        for (int t = 0; t < 4; t++) {
            n0[t] = (v0 && ch < 3) ? A0[(ch + 1) * 16 + t * 4 + c] : z4;
            n1[t] = (v1 && ch < 3) ? A1[(ch + 1) * 16 + t * 4 + c] : z4;
        }
        #pragma unroll
        for (int t = 0; t < 4; t++) {
            int wnd = ch * 4 + t;
            uint32_t a00 = f2tf32(b0[t].x), a01 = f2tf32(b0[t].y), a02 = f2tf32(b0[t].z), a03 = f2tf32(b0[t].w);
            uint32_t a10 = f2tf32(b1[t].x), a11 = f2tf32(b1[t].y), a12 = f2tf32(b1[t].z), a13 = f2tf32(b1[t].w);
            const uint32_t* bA = sB + (wnd * 16 + 4 * c) * S1;
            #pragma unroll
            for (int nt = 0; nt < 6; nt++)
                mma_tf32(acc[nt], a00, a10, a01, a11, bA[nt * 8 + g], bA[S1 + nt * 8 + g]);
            #pragma unroll
            for (int nt = 0; nt < 6; nt++)
                mma_tf32(acc[nt], a02, a12, a03, a13, bA[2 * S1 + nt * 8 + g], bA[3 * S1 + nt * 8 + g]);
        }
        #pragma unroll
        for (int t = 0; t < 4; t++) { b0[t] = n0[t]; b1[t] = n1[t]; }
    }
    #pragma unroll
    for (int nt = 0; nt < 4; nt++) {
        int col = nt * 8 + c * 2;
        if (v0) *(float2*)&g_h1[row0 * F1 + col] = make_float2(acc[nt][0], acc[nt][1]);
        if (v1) *(float2*)&g_h1[row1 * F1 + col] = make_float2(acc[nt][2], acc[nt][3]);
    }
    if (v0) *(float2*)&g_el1[row0 * H1 + 2 * c] = make_float2(acc[4][0], acc[4][1]);
    if (v1) *(float2*)&g_el1[row1 * H1 + 2 * c] = make_float2(acc[4][2], acc[4][3]);
    if (v0) *(float2*)&g_er1[row0 * H1 + 2 * c] = make_float2(acc[5][0], acc[5][1]);
    if (v1) *(float2*)&g_er1[row1 * H1 + 2 * c] = make_float2(acc[5][2], acc[5][3]);
}

// ---------------- GEMM2 (tf32 mma, fused h2p/el2/er2, chunk prefetch) ----------------
// N=56 (7 n-tiles): cols 0..46 h2, 47 pad(0), 48 el2, 49 er2, 50..55 pad.
#define S2 58
__global__ void __launch_bounds__(256) k_gemm2() {
    extern __shared__ uint32_t sm2[];
    uint32_t* sB = sm2;                      // [256][S2]
    int tx = threadIdx.x, lane = tx & 31, w = tx >> 5;
    for (int i = tx; i < FIN * 50; i += 256) {
        int k = i / 50, n = i - k * 50;
        sB[k * S2 + n] = f2tf32(g_B2ext[i]);
    }
    for (int i = tx; i < FIN * 6; i += 256) {
        int k = i / 6, n = 50 + (i - k * 6);
        sB[k * S2 + n] = 0u;
    }
    __syncthreads();

    int g = lane >> 2, c = lane & 3;
    int row0 = blockIdx.x * 128 + w * 16 + g;
    int row1 = row0 + 8;
    bool v0 = row0 < Nn, v1 = row1 < Nn;
    const float4* A0 = (const float4*)(g_r1 + (size_t)row0 * FIN);
    const float4* A1 = (const float4*)(g_r1 + (size_t)row1 * FIN);
    const float4 z4 = make_float4(0.f, 0.f, 0.f, 0.f);

    float acc[7][4];
    #pragma unroll
    for (int nt = 0; nt < 7; nt++)
        #pragma unroll
        for (int j = 0; j < 4; j++) acc[nt][j] = 0.f;

    float4 b0[4], b1[4];
    #pragma unroll
    for (int t = 0; t < 4; t++) {
        b0[t] = v0 ? A0[t * 4 + c] : z4;
        b1[t] = v1 ? A1[t * 4 + c] : z4;
    }
    #pragma unroll
    for (int ch = 0; ch < 4; ch++) {
        float4 n0[4], n1[4];
        #pragma unroll
        for (int t = 0; t < 4; t++) {
            n0[t] = (v0 && ch < 3) ? A0[(ch + 1) * 16 + t * 4 + c] : z4;
            n1[t] = (v1 && ch < 3) ? A1[(ch + 1) * 16 + t * 4 + c] : z4;
        }
        #pragma unroll
        for (int t = 0; t < 4; t++) {
            int wnd = ch * 4 + t;
            uint32_t a00 = f2tf32(b0[t].x), a01 = f2tf32(b0[t].y), a02 = f2tf32(b0[t].z), a03 = f2tf32(b0[t].w);
            uint32_t a10 = f2tf32(b1[t].x), a11 = f2tf32(b1[t].y), a12 = f2tf32(b1[t].z), a13 = f2tf32(b1[t].w);
            const uint32_t* bA = sB + (wnd * 16 + 4 * c) * S2;
            #pragma unroll
            for (int nt = 0; nt < 7; nt++)
                mma_tf32(acc[nt], a00, a10, a01, a11, bA[nt * 8 + g], bA[S2 + nt * 8 + g]);
            #pragma unroll
            for (int nt = 0; nt < 7; nt++)
                mma_tf32(acc[nt], a02, a12, a03, a13, bA[2 * S2 + nt * 8 + g], bA[3 * S2 + nt * 8 + g]);
        }
        #pragma unroll
        for (int t = 0; t < 4; t++) { b0[t] = n0[t]; b1[t] = n1[t]; }
    }
    #pragma unroll
    for (int nt = 0; nt < 6; nt++) {
        int col = nt * 8 + c * 2;
        if (v0) *(float2*)&g_h2p[(size_t)row0 * 48 + col] = make_float2(acc[nt][0], acc[nt][1]);
        if (v1) *(float2*)&g_h2p[(size_t)row1 * 48 + col] = make_float2(acc[nt][2], acc[nt][3]);
    }
    if (c == 0) {   // nt=6, cols 48/49 -> el2/er2
        if (v0) { g_el2[row0] = acc[6][0]; g_er2[row0] = acc[6][1]; }
        if (v1) { g_el2[row1] = acc[6][2]; g_er2[row1] = acc[6][3]; }
    }
}

// ---------------- layer-1 aggregation + bias + ELU -> r1 ----------------
__global__ void k_agg1(const float* __restrict__ b1) {
    __shared__ float ws[8][32 * 8];    // [warp][edge][head] weights
    int wid = threadIdx.x >> 5, lane = threadIdx.x & 31;
    int i = blockIdx.x * 8 + wid;

    float el_own = (lane < H1) ? g_el1[i * H1 + lane] : 0.f;
    float elh[H1];
    #pragma unroll
    for (int h = 0; h < H1; h++) elh[h] = __shfl_sync(0xffffffffu, el_own, h);

    float acc[H1], denp[H1];
    #pragma unroll
    for (int h = 0; h < H1; h++) { acc[h] = 0.f; denp[h] = 0.f; }

    int beg = g_rowptr[i], end = g_rowptr[i + 1];
    for (int base = beg; base < end; base += 32) {
        int nb = min(32, end - base);
        int dstl = (lane < nb) ? g_csr_dst[base + lane] : 0;
        float w_own[H1];
        if (lane < nb) {
            const float4* er4 = (const float4*)(g_er1 + (size_t)dstl * H1);
            float4 ea = er4[0], eb = er4[1];
            float er_[H1] = {ea.x, ea.y, ea.z, ea.w, eb.x, eb.y, eb.z, eb.w};
            #pragma unroll
            for (int h = 0; h < H1; h++) {
                float a = elh[h] + er_[h];
                float lr = a > 0.f ? a : 0.2f * a;
                float wv = __expf(lr);
                w_own[h] = wv;
                denp[h] += wv;
            }
        } else {
            #pragma unroll
            for (int h = 0; h < H1; h++) w_own[h] = 0.f;
        }
        float4* wrow = (float4*)&ws[wid][lane * 8];
        wrow[0] = make_float4(w_own[0], w_own[1], w_own[2], w_own[3]);
        wrow[1] = make_float4(w_own[4], w_own[5], w_own[6], w_own[7]);
        __syncwarp();
        // unroll x4: 4 independent gathers in flight; tail lanes have zero
        // weights and dst=0, so extra iterations contribute exactly 0.
        for (int j = 0; j < nb; j += 4) {
            int d0 = __shfl_sync(0xffffffffu, dstl, j);
            int d1 = __shfl_sync(0xffffffffu, dstl, j + 1);
            int d2 = __shfl_sync(0xffffffffu, dstl, j + 2);
            int d3 = __shfl_sync(0xffffffffu, dstl, j + 3);
            float hv0 = g_h1[d0 * F1 + lane];
            float hv1 = g_h1[d1 * F1 + lane];
            float hv2 = g_h1[d2 * F1 + lane];
            float hv3 = g_h1[d3 * F1 + lane];
            const float4* wj = (const float4*)&ws[wid][j * 8];
            #pragma unroll
            for (int u = 0; u < 4; u++) {
                float hv = (u == 0) ? hv0 : (u == 1) ? hv1 : (u == 2) ? hv2 : hv3;
                float4 wa = wj[u * 2], wb = wj[u * 2 + 1];
                acc[0] = fmaf(wa.x, hv, acc[0]);
                acc[1] = fmaf(wa.y, hv, acc[1]);
                acc[2] = fmaf(wa.z, hv, acc[2]);
                acc[3] = fmaf(wa.w, hv, acc[3]);
                acc[4] = fmaf(wb.x, hv, acc[4]);
                acc[5] = fmaf(wb.y, hv, acc[5]);
                acc[6] = fmaf(wb.z, hv, acc[6]);
                acc[7] = fmaf(wb.w, hv, acc[7]);
            }
        }
        __syncwarp();
    }
    float bb = b1[lane];
    #pragma unroll
    for (int h = 0; h < H1; h++) {
        float t = denp[h];
        #pragma unroll
        for (int d = 16; d > 0; d >>= 1) t += __shfl_xor_sync(0xffffffffu, t, d);
        float o = acc[h] / fmaxf(t, 1e-12f) + bb;
        float e = o > 0.f ? o : (__expf(o) - 1.f);   // ELU
        g_r1[(size_t)i * NHID + h * F1 + lane] = e;
    }
}

// ---------------- layer-2 aggregation + bias + log_softmax -> out ----------------
// lanes 0..23 each own class columns {2l, 2l+1} of padded h2p (float2 gathers).
__global__ void k_agg2(const float* __restrict__ b2, float* __restrict__ out) {
    int wid = threadIdx.x >> 5, lane = threadIdx.x & 31;
    int i = blockIdx.x * 8 + wid;
    float el = g_el2[i];
    float accx = 0.f, accy = 0.f, denp = 0.f;
    int beg = g_rowptr[i], end = g_rowptr[i + 1];
    for (int base = beg; base < end; base += 32) {
        int nb = min(32, end - base);
        int dstl = (lane < nb) ? g_csr_dst[base + lane] : 0;
        float wl_ = 0.f;
        if (lane < nb) {
            float a = el + g_er2[dstl];
            float lr = a > 0.f ? a : 0.2f * a;
            wl_ = __expf(lr);
            denp += wl_;
        }
        for (int j = 0; j < nb; j += 4) {
            #pragma unroll
            for (int u = 0; u < 4; u++) {
                int d = __shfl_sync(0xffffffffu, dstl, j + u);
                float wv = __shfl_sync(0xffffffffu, wl_, j + u);
                if (lane < 24) {
                    float2 hv = *(const float2*)&g_h2p[(size_t)d * 48 + 2 * lane];
                    accx = fmaf(wv, hv.x, accx);
                    accy = fmaf(wv, hv.y, accy);
                }
            }
        }
    }
    float den = denp;
    #pragma unroll
    for (int d = 16; d > 0; d >>= 1) den += __shfl_xor_sync(0xffffffffu, den, d);
    den = fmaxf(den, 1e-12f);
    float vx = -3.0e38f, vy = -3.0e38f;
    if (lane < 24) {
        vx = accx / den + b2[2 * lane];
        vy = (2 * lane + 1 < NC) ? (accy / den + b2[2 * lane + 1]) : -3.0e38f;
    }
    float m = fmaxf(vx, vy);
    #pragma unroll
    for (int d = 16; d > 0; d >>= 1) m = fmaxf(m, __shfl_xor_sync(0xffffffffu, m, d));
    float s = 0.f;
    if (lane < 24) {
        s = __expf(vx - m);
        if (2 * lane + 1 < NC) s += __expf(vy - m);
    }
    #pragma unroll
    for (int d = 16; d > 0; d >>= 1) s += __shfl_xor_sync(0xffffffffu, s, d);
    float ls = logf(s);
    if (lane < 24) {
        out[(size_t)i * NC + 2 * lane] = vx - m - ls;
        if (2 * lane + 1 < NC) out[(size_t)i * NC + 2 * lane + 1] = vy - m - ls;
    }
}

// ---------------- launch ----------------
extern "C" void kernel_launch(void* const* d_in, const int* in_sizes, int n_in,
                              void* d_out, int out_size) {
    const float* x    = (const float*)d_in[0];
    const int*   esrc = (const int*)  d_in[1];
    const int*   edst = (const int*)  d_in[2];
    const float* W1   = (const float*)d_in[3];
    const float* Wl1  = (const float*)d_in[4];
    const float* Wr1  = (const float*)d_in[5];
    const float* b1   = (const float*)d_in[6];
    const float* W2   = (const float*)d_in[7];
    const float* Wl2  = (const float*)d_in[8];
    const float* Wr2  = (const float*)d_in[9];
    const float* b2   = (const float*)d_in[10];
    float* out = (float*)d_out;

    const int smem1 = FIN * S1 * 4;   // 50 KB
    const int smem2 = FIN * S2 * 4;   // 58 KB
    cudaFuncSetAttribute(k_gemm1, cudaFuncAttributeMaxDynamicSharedMemorySize, smem1);
    cudaFuncSetAttribute(k_gemm2, cudaFuncAttributeMaxDynamicSharedMemorySize, smem2);

    int n_scan = Nn + 1;
    int nb = (n_scan + 1023) / 1024;           // 49

    // order chosen so launch #4 (the profiled slot) = k_gemm1
    k_prep1<<<1, 256>>>(W1, Wl1, Wr1);
    k_zero_counts<<<(Nn + 1 + 255) / 256, 256>>>();
    k_count<<<Ee / 256, 256>>>(esrc);
    k_gemm1<<<(Nn + 127) / 128, 256, smem1>>>(x);   // #4 <- profiled
    k_scan_blocks<<<nb, 1024>>>(n_scan);
    k_finalize_scan<<<nb, 1024>>>(n_scan);
    k_scatter<<<Ee / 256, 256>>>(esrc, edst);
    k_agg1<<<Nn / 8, 256>>>(b1);

    k_prep2<<<1, 256>>>(W2, Wl2, Wr2);
    k_gemm2<<<(Nn + 127) / 128, 256, smem2>>>();
    k_agg2<<<Nn / 8, 256>>>(b2, out);
}